// round 9
// baseline (speedup 1.0000x reference)
#include <cuda_runtime.h>
#include <cuda_bf16.h>
#include <cstdint>

#define B_ 4
#define T_ 2048
#define C_ 1024
#define H_ 16
#define D_ 64
#define M_ (B_*T_)   // 8192

// ---------------------------------------------------------------------------
// Scratch (__device__ globals; referenced ONLY from device code — host-side
// use of these symbols yields the host shadow (ATS zeros): round-5/6 bug)
// ---------------------------------------------------------------------------
__device__ float g_q[(size_t)B_*H_*T_*D_];
__device__ float g_k[(size_t)B_*H_*T_*D_];
__device__ float g_v[(size_t)B_*H_*T_*D_];
__device__ __align__(16) unsigned short g_xhi[(size_t)M_*C_];  // x split, then y split
__device__ __align__(16) unsigned short g_xlo[(size_t)M_*C_];
__device__ __align__(16) unsigned short g_whiT[(size_t)4*C_*C_];  // [slot][n][k]
__device__ __align__(16) unsigned short g_wloT[(size_t)4*C_*C_];

// ---------------------------------------------------------------------------
// Base-target PTX helpers
// ---------------------------------------------------------------------------
__device__ __forceinline__ uint32_t s2u(const void* p) {
    uint32_t a;
    asm("{ .reg .u64 t; cvta.to.shared.u64 t, %1; cvt.u32.u64 %0, t; }" : "=r"(a) : "l"(p));
    return a;
}

__device__ __forceinline__ void ldsm_x4(uint32_t addr, uint32_t* r) {
    asm volatile("ldmatrix.sync.aligned.m8n8.x4.shared.b16 {%0,%1,%2,%3}, [%4];"
                 : "=r"(r[0]), "=r"(r[1]), "=r"(r[2]), "=r"(r[3]) : "r"(addr));
}
__device__ __forceinline__ void ldsm_x4t(uint32_t addr, uint32_t* r) {
    asm volatile("ldmatrix.sync.aligned.m8n8.x4.trans.shared.b16 {%0,%1,%2,%3}, [%4];"
                 : "=r"(r[0]), "=r"(r[1]), "=r"(r[2]), "=r"(r[3]) : "r"(addr));
}

__device__ __forceinline__ void mma_bf16(float* c, const uint32_t* a, uint32_t b0, uint32_t b1) {
    asm("mma.sync.aligned.m16n8k16.row.col.f32.bf16.bf16.f32 "
        "{%0,%1,%2,%3}, {%4,%5,%6,%7}, {%8,%9}, {%0,%1,%2,%3};"
        : "+f"(c[0]), "+f"(c[1]), "+f"(c[2]), "+f"(c[3])
        : "r"(a[0]), "r"(a[1]), "r"(a[2]), "r"(a[3]), "r"(b0), "r"(b1));
}

__device__ __forceinline__ void cp16(uint32_t saddr, const void* g) {
    asm volatile("cp.async.cg.shared.global [%0], [%1], 16;" :: "r"(saddr), "l"(g));
}
#define CP_COMMIT() asm volatile("cp.async.commit_group;")

// pack two floats to bf16x2: low 16 bits = lo arg, high 16 bits = hi arg
__device__ __forceinline__ uint32_t packbf(float lo, float hi) {
    uint32_t r;
    asm("cvt.rn.bf16x2.f32 %0, %1, %2;" : "=r"(r) : "f"(hi), "f"(lo));
    return r;
}

// ---------------------------------------------------------------------------
// Conversion pre-passes
// ---------------------------------------------------------------------------
__global__ __launch_bounds__(256) void conv_x_k(const float* __restrict__ in, int n4)
{
    int i = blockIdx.x * blockDim.x + threadIdx.x;
    if (i >= n4) return;
    float4 v = ((const float4*)in)[i];
    uint32_t h0 = packbf(v.x, v.y);
    uint32_t h1 = packbf(v.z, v.w);
    float r0 = v.x - __uint_as_float(h0 << 16);
    float r1 = v.y - __uint_as_float(h0 & 0xFFFF0000u);
    float r2 = v.z - __uint_as_float(h1 << 16);
    float r3 = v.w - __uint_as_float(h1 & 0xFFFF0000u);
    ((uint2*)g_xhi)[i] = make_uint2(h0, h1);
    ((uint2*)g_xlo)[i] = make_uint2(packbf(r0, r1), packbf(r2, r3));
}

// W[k][n] -> WT hi/lo [n][k]
__global__ void conv_w_t_k(const float* __restrict__ W, int slot)
{
    __shared__ float tile[32][33];
    const int n0 = blockIdx.x * 32, k0 = blockIdx.y * 32;
    const int tx = threadIdx.x, ty = threadIdx.y;
    unsigned short* hiT = g_whiT + (size_t)slot * C_ * C_;
    unsigned short* loT = g_wloT + (size_t)slot * C_ * C_;
    for (int r = ty; r < 32; r += 8)
        tile[r][tx] = W[(size_t)(k0 + r) * C_ + n0 + tx];
    __syncthreads();
    for (int r = ty; r < 32; r += 8) {
        float v = tile[tx][r];
        __nv_bfloat16 h = __float2bfloat16_rn(v);
        float res = v - __bfloat162float(h);
        size_t o = (size_t)(n0 + r) * C_ + k0 + tx;
        hiT[o] = __bfloat16_as_ushort(h);
        loT[o] = __bfloat16_as_ushort(__float2bfloat16_rn(res));
    }
}

// ---------------------------------------------------------------------------
// GEMM body (split-bf16, mma.sync, 3-stage cp.async pipeline).
// dst 0/1/2: head-scatter fp32 into g_q/g_k/g_v; dst 3: plain fp32 to OutP.
// smem: 3 stages x {Ahi,Alo,Bhi,Blo} x 128 rows x 80B = 122880 B
// ---------------------------------------------------------------------------
__device__ __forceinline__
void gemm_body(int dst, const float* __restrict__ bias, float* __restrict__ OutP)
{
    extern __shared__ __align__(16) char sm[];
    const uint32_t smb = s2u(sm);
    const int tid = threadIdx.x, lane = tid & 31, wid = tid >> 5;
    const int warp_m = wid >> 2, warp_n = wid & 3;
    const int m0 = blockIdx.x * 128, n0 = blockIdx.y * 128;

    const unsigned short* Ahi = g_xhi;
    const unsigned short* Alo = g_xlo;
    const unsigned short* Bhi = g_whiT + (size_t)dst * C_ * C_;
    const unsigned short* Blo = g_wloT + (size_t)dst * C_ * C_;

    const unsigned short* gsrc[8];
    uint32_t sdst[8];
#pragma unroll
    for (int i = 0; i < 8; i++) {
        const int op  = i >> 1;                      // 0 Ahi,1 Alo,2 Bhi,3 Blo
        const int row = (tid >> 2) + (i & 1) * 64;
        const int seg = tid & 3;
        const unsigned short* base = (op == 0) ? Ahi : (op == 1) ? Alo : (op == 2) ? Bhi : Blo;
        const int grow = ((op < 2) ? m0 : n0) + row;
        gsrc[i] = base + (size_t)grow * C_ + seg * 8;
        sdst[i] = smb + op * 10240 + row * 80 + seg * 16;
    }

    float c[4][4][4];
#pragma unroll
    for (int mt = 0; mt < 4; mt++)
#pragma unroll
        for (int nt = 0; nt < 4; nt++)
#pragma unroll
            for (int e = 0; e < 4; e++) c[mt][nt][e] = 0.f;

    // prologue: stages 0,1
#pragma unroll
    for (int i = 0; i < 8; i++) cp16(sdst[i], gsrc[i]);
    CP_COMMIT();
#pragma unroll
    for (int i = 0; i < 8; i++) cp16(sdst[i] + 40960, gsrc[i] + 32);
    CP_COMMIT();

    for (int it = 0; it < 32; ++it) {
        if (it < 31) asm volatile("cp.async.wait_group 1;");
        else         asm volatile("cp.async.wait_group 0;");
        __syncthreads();   // single barrier/iter: covers stage-ready + buffer reuse

        if (it + 2 < 32) {
            const uint32_t off = ((it + 2) % 3) * 40960;
#pragma unroll
            for (int i = 0; i < 8; i++) cp16(sdst[i] + off, gsrc[i] + (it + 2) * 32);
            CP_COMMIT();
        }

        const uint32_t sb = smb + (it % 3) * 40960;
#pragma unroll
        for (int kk = 0; kk < 2; kk++) {
            uint32_t ah[4][4], al[4][4], bh[4][2], bl[4][2];
#pragma unroll
            for (int mt = 0; mt < 4; mt++) {
                int row = warp_m * 64 + mt * 16 + (lane & 7) + ((lane >> 3) & 1) * 8;
                uint32_t byte = (uint32_t)(row * 80 + kk * 32 + (lane >> 4) * 16);
                ldsm_x4(sb + byte, ah[mt]);
                ldsm_x4(sb + 10240 + byte, al[mt]);
            }
#pragma unroll
            for (int p = 0; p < 2; p++) {
                int row = warp_n * 32 + p * 16 + (lane & 7) + ((lane >> 3) & 1) * 8;
                uint32_t byte = (uint32_t)(row * 80 + kk * 32 + (lane >> 4) * 16);
                uint32_t r[4], u[4];
                ldsm_x4(sb + 20480 + byte, r);
                ldsm_x4(sb + 30720 + byte, u);
                bh[2*p][0] = r[0]; bh[2*p][1] = r[2];
                bh[2*p+1][0] = r[1]; bh[2*p+1][1] = r[3];
                bl[2*p][0] = u[0]; bl[2*p][1] = u[2];
                bl[2*p+1][0] = u[1]; bl[2*p+1][1] = u[3];
            }
#pragma unroll
            for (int mt = 0; mt < 4; mt++)
#pragma unroll
                for (int nt = 0; nt < 4; nt++) {
                    mma_bf16(c[mt][nt], ah[mt], bh[nt][0], bh[nt][1]);
                    mma_bf16(c[mt][nt], ah[mt], bl[nt][0], bl[nt][1]);
                    mma_bf16(c[mt][nt], al[mt], bh[nt][0], bh[nt][1]);
                }
        }
    }

    // fp32 epilogue
#pragma unroll
    for (int mt = 0; mt < 4; mt++) {
        const int r = m0 + warp_m * 64 + mt * 16 + (lane >> 2);
#pragma unroll
        for (int nt = 0; nt < 4; nt++) {
            const int col = n0 + warp_n * 32 + nt * 8 + (lane & 3) * 2;
            const float bb0 = bias[col], bb1 = bias[col + 1];
#pragma unroll
            for (int half = 0; half < 2; half++) {
                const int m = r + half * 8;
                float v0 = c[mt][nt][half * 2 + 0] + bb0;
                float v1 = c[mt][nt][half * 2 + 1] + bb1;
                if (dst == 3) {
                    *(float2*)(OutP + (size_t)m * C_ + col) = make_float2(v0, v1);
                } else {
                    float* O = (dst == 0) ? g_q : (dst == 1) ? g_k : g_v;
                    const int b = m >> 11, t = m & (T_ - 1);
                    const int h = col >> 6, d = col & 63;
                    *(float2*)(O + (((size_t)(b * H_ + h)) * T_ + t) * D_ + d) = make_float2(v0, v1);
                }
            }
        }
    }
}

__global__ __launch_bounds__(256)
void gemm_qkv(const float* __restrict__ bq, const float* __restrict__ bk,
              const float* __restrict__ bv)
{
    const int z = blockIdx.z;
    const float* bias = (z == 0) ? bq : (z == 1) ? bk : bv;
    gemm_body(z, bias, nullptr);
}

__global__ __launch_bounds__(256)
void gemm_out(const float* __restrict__ bias, float* __restrict__ OutP)
{
    gemm_body(3, bias, OutP);
}

// ---------------------------------------------------------------------------
// Causal flash attention via mma.sync. 8 warps, 128 q-rows x 64 k-cols tiles.
// fp32 K/V staged via double-buffered cp.async, converted to split-bf16 tiles.
// Q scaled 1/8 at stage-in. Output written split directly to g_xhi/g_xlo.
// smem: KH|KL|VH|VL (4 x 9216) + 2 x (K 16384 + V 16384) = 102400 B dynamic
// ---------------------------------------------------------------------------
#define AT_KH 0u
#define AT_KL 9216u
#define AT_VH 18432u
#define AT_VL 27648u
#define AT_ST 36864u         // fp32 staging base; stage stride 32768 (K+V)

__global__ __launch_bounds__(256)
void attn_mma()
{
    extern __shared__ __align__(16) char sm[];
    const uint32_t smb = s2u(sm);
    const int tid = threadIdx.x, lane = tid & 31, warp = tid >> 5;
    const int qb = blockIdx.x, bh = blockIdx.y;

    const float* Qg = g_q + (size_t)bh * T_ * D_ + (size_t)qb * 128 * D_;
    const float* Kg = g_k + (size_t)bh * T_ * D_;
    const float* Vg = g_v + (size_t)bh * T_ * D_;

    // ---- stage Q (scaled 1/8): rows 0-63 -> KH/KL, rows 64-127 -> VH/VL ----
#pragma unroll
    for (int i = 0; i < 8; i++) {
        int idx = i * 256 + tid;                 // float4 idx, 2048 total
        int row = idx >> 4, c8 = (idx & 15) * 8;
        float4 v = ((const float4*)Qg)[idx];
        v.x *= 0.125f; v.y *= 0.125f; v.z *= 0.125f; v.w *= 0.125f;
        uint32_t h0 = packbf(v.x, v.y), h1 = packbf(v.z, v.w);
        uint32_t l0 = packbf(v.x - __uint_as_float(h0 << 16),
                             v.y - __uint_as_float(h0 & 0xFFFF0000u));
        uint32_t l1 = packbf(v.z - __uint_as_float(h1 << 16),
                             v.w - __uint_as_float(h1 & 0xFFFF0000u));
        uint32_t bhc = (row < 64) ? AT_KH : AT_VH;
        uint32_t blc = (row < 64) ? AT_KL : AT_VL;
        int lr = row & 63;
        *(uint2*)(sm + bhc + lr * 144 + c8) = make_uint2(h0, h1);
        *(uint2*)(sm + blc + lr * 144 + c8) = make_uint2(l0, l1);
    }
    __syncthreads();

    uint32_t qhf[4][4], qlf[4][4];
    {
        const uint32_t qbh = (warp < 4) ? AT_KH : AT_VH;
        const uint32_t qbl = (warp < 4) ? AT_KL : AT_VL;
        const int wl = (warp & 3) * 16;
#pragma unroll
        for (int kk = 0; kk < 4; kk++) {
            int row = wl + (lane & 7) + ((lane >> 3) & 1) * 8;
            uint32_t byte = (uint32_t)(row * 144 + kk * 32 + (lane >> 4) * 16);
            ldsm_x4(smb + qbh + byte, qhf[kk]);
            ldsm_x4(smb + qbl + byte, qlf[kk]);
        }
    }
    __syncthreads();

    float o[8][4];
#pragma unroll
    for (int j = 0; j < 8; j++)
#pragma unroll
        for (int e = 0; e < 4; e++) o[j][e] = 0.f;
    float m0r = -1e30f, m1r = -1e30f, l0r = 0.f, l1r = 0.f;

    const int kb_last = 2 * qb + 1;
    const int R = qb * 128 + warp * 16;          // warp's first q-row (global)
    const int grow = R + (lane >> 2);

    // issue fp32 K/V tile kb into staging buffer sel
    auto issue_kv = [&](int kb, int sel) {
        const uint32_t db = smb + AT_ST + sel * 32768u;
        const float* Ks = Kg + (size_t)kb * 64 * D_;
        const float* Vs = Vg + (size_t)kb * 64 * D_;
#pragma unroll
        for (int i = 0; i < 4; i++) {
            int f = i * 256 + tid;
            cp16(db + f * 16, Ks + f * 4);
            cp16(db + 16384 + f * 16, Vs + f * 4);
        }
    };

    issue_kv(0, 0);
    CP_COMMIT();

    for (int kb = 0; kb <= kb_last; kb++) {
        if (kb < kb_last) { issue_kv(kb + 1, (kb + 1) & 1); CP_COMMIT(); }
        if (kb < kb_last) asm volatile("cp.async.wait_group 1;");
        else              asm volatile("cp.async.wait_group 0;");
        __syncthreads();

        // ---- convert staged fp32 K/V -> split-bf16 tiles ----
        {
            const char* db = sm + AT_ST + (kb & 1) * 32768u;
            const float4* Ks = (const float4*)db;
            const float4* Vs = (const float4*)(db + 16384);
#pragma unroll
            for (int i = 0; i < 4; i++) {
                int f = i * 256 + tid;
                int row = f >> 4, c8 = (f & 15) * 8;
                {
                    float4 v = Ks[f];
                    uint32_t h0 = packbf(v.x, v.y), h1 = packbf(v.z, v.w);
                    uint32_t l0 = packbf(v.x - __uint_as_float(h0 << 16),
                                         v.y - __uint_as_float(h0 & 0xFFFF0000u));
                    uint32_t l1 = packbf(v.z - __uint_as_float(h1 << 16),
                                         v.w - __uint_as_float(h1 & 0xFFFF0000u));
                    *(uint2*)(sm + AT_KH + row * 144 + c8) = make_uint2(h0, h1);
                    *(uint2*)(sm + AT_KL + row * 144 + c8) = make_uint2(l0, l1);
                }
                {
                    float4 v = Vs[f];
                    uint32_t h0 = packbf(v.x, v.y), h1 = packbf(v.z, v.w);
                    uint32_t l0 = packbf(v.x - __uint_as_float(h0 << 16),
                                         v.y - __uint_as_float(h0 & 0xFFFF0000u));
                    uint32_t l1 = packbf(v.z - __uint_as_float(h1 << 16),
                                         v.w - __uint_as_float(h1 & 0xFFFF0000u));
                    *(uint2*)(sm + AT_VH + row * 144 + c8) = make_uint2(h0, h1);
                    *(uint2*)(sm + AT_VL + row * 144 + c8) = make_uint2(l0, l1);
                }
            }
        }
        __syncthreads();

        const int Ckb = kb * 64;
        if (Ckb < R + 16) {                       // warp has unmasked columns
            // ---- S = Q K^T (3-term split) ----
            float s[8][4];
#pragma unroll
            for (int j = 0; j < 8; j++)
#pragma unroll
                for (int e = 0; e < 4; e++) s[j][e] = 0.f;

#pragma unroll
            for (int kk = 0; kk < 4; kk++) {
                uint32_t kh[8][2], kl[8][2];
#pragma unroll
                for (int p = 0; p < 4; p++) {
                    int row = p * 16 + (lane & 7) + ((lane >> 3) & 1) * 8;
                    uint32_t byte = (uint32_t)(row * 144 + kk * 32 + (lane >> 4) * 16);
                    uint32_t r[4], u[4];
                    ldsm_x4(smb + AT_KH + byte, r);
                    ldsm_x4(smb + AT_KL + byte, u);
                    kh[2*p][0] = r[0]; kh[2*p][1] = r[2];
                    kh[2*p+1][0] = r[1]; kh[2*p+1][1] = r[3];
                    kl[2*p][0] = u[0]; kl[2*p][1] = u[2];
                    kl[2*p+1][0] = u[1]; kl[2*p+1][1] = u[3];
                }
#pragma unroll
                for (int j = 0; j < 8; j++) {
                    mma_bf16(s[j], qhf[kk], kh[j][0], kh[j][1]);
                    mma_bf16(s[j], qhf[kk], kl[j][0], kl[j][1]);
                    mma_bf16(s[j], qlf[kk], kh[j][0], kh[j][1]);
                }
            }

            // ---- causal mask (global row/col compare) ----
            if (Ckb + 63 > R) {
#pragma unroll
                for (int j = 0; j < 8; j++) {
#pragma unroll
                    for (int e = 0; e < 4; e++) {
                        int col = Ckb + j * 8 + (lane & 3) * 2 + (e & 1);
                        int rw  = grow + (e >> 1) * 8;
                        if (col > rw) s[j][e] = -1e30f;
                    }
                }
            }

            // ---- online softmax ----
            float mt0 = -1e30f, mt1 = -1e30f;
#pragma unroll
            for (int j = 0; j < 8; j++) {
                mt0 = fmaxf(mt0, fmaxf(s[j][0], s[j][1]));
                mt1 = fmaxf(mt1, fmaxf(s[j][2], s[j][3]));
            }
            mt0 = fmaxf(mt0, __shfl_xor_sync(0xffffffffu, mt0, 1));
            mt0 = fmaxf(mt0, __shfl_xor_sync(0xffffffffu, mt0, 2));
            mt1 = fmaxf(mt1, __shfl_xor_sync(0xffffffffu, mt1, 1));
            mt1 = fmaxf(mt1, __shfl_xor_sync(0xffffffffu, mt1, 2));
            const float mn0 = fmaxf(m0r, mt0), mn1 = fmaxf(m1r, mt1);
            const float al0 = __expf(m0r - mn0), al1 = __expf(m1r - mn1);

            float ls0 = 0.f, ls1 = 0.f;
            uint32_t aph[4][4], apl[4][4];
#pragma unroll
            for (int j = 0; j < 8; j++) {
                float p0 = __expf(s[j][0] - mn0);
                float p1 = __expf(s[j][1] - mn0);
                float p2 = __expf(s[j][2] - mn1);
                float p3 = __expf(s[j][3] - mn1);
                ls0 += p0 + p1;
                ls1 += p2 + p3;
                uint32_t h01 = packbf(p0, p1), h23 = packbf(p2, p3);
                float e0 = p0 - __uint_as_float(h01 << 16);
                float e1 = p1 - __uint_as_float(h01 & 0xFFFF0000u);
                float e2 = p2 - __uint_as_float(h23 << 16);
                float e3 = p3 - __uint_as_float(h23 & 0xFFFF0000u);
                uint32_t l01 = packbf(e0, e1), l23 = packbf(e2, e3);
                const int kk = j >> 1;
                if ((j & 1) == 0) {
                    aph[kk][0] = h01; aph[kk][1] = h23;
                    apl[kk][0] = l01; apl[kk][1] = l23;
                } else {
                    aph[kk][2] = h01; aph[kk][3] = h23;
                    apl[kk][2] = l01; apl[kk][3] = l23;
                }
            }
            ls0 += __shfl_xor_sync(0xffffffffu, ls0, 1);
            ls0 += __shfl_xor_sync(0xffffffffu, ls0, 2);
            ls1 += __shfl_xor_sync(0xffffffffu, ls1, 1);
            ls1 += __shfl_xor_sync(0xffffffffu, ls1, 2);
            l0r = l0r * al0 + ls0;
            l1r = l1r * al1 + ls1;
            m0r = mn0; m1r = mn1;

#pragma unroll
            for (int j = 0; j < 8; j++) {
                o[j][0] *= al0; o[j][1] *= al0;
                o[j][2] *= al1; o[j][3] *= al1;
            }

            // ---- O += P V (3-term split) ----
#pragma unroll
            for (int kk = 0; kk < 4; kk++) {
#pragma unroll
                for (int j = 0; j < 8; j += 2) {
                    int row = kk * 16 + (lane & 7) + ((lane >> 3) & 1) * 8;
                    uint32_t byte = (uint32_t)(row * 144 + (j + (lane >> 4)) * 16);
                    uint32_t r[4], u[4];
                    ldsm_x4t(smb + AT_VH + byte, r);
                    ldsm_x4t(smb + AT_VL + byte, u);
                    mma_bf16(o[j],     aph[kk], r[0], r[1]);
                    mma_bf16(o[j],     aph[kk], u[0], u[1]);
                    mma_bf16(o[j],     apl[kk], r[0], r[1]);
                    mma_bf16(o[j + 1], aph[kk], r[2], r[3]);
                    mma_bf16(o[j + 1], aph[kk], u[2], u[3]);
                    mma_bf16(o[j + 1], apl[kk], r[2], r[3]);
                }
            }
        }
    }

    // ---- epilogue: normalize, write split y directly into g_xhi/g_xlo ----
    const float inv0 = 1.f / l0r, inv1 = 1.f / l1r;
    const int b = bh >> 4, h = bh & 15;
    const int r0g = qb * 128 + warp * 16 + (lane >> 2);
#pragma unroll
    for (int j = 0; j < 8; j++) {
        const int col = h * 64 + j * 8 + (lane & 3) * 2;
        float v0 = o[j][0] * inv0, v1 = o[j][1] * inv0;
        float v2 = o[j][2] * inv1, v3 = o[j][3] * inv1;
        size_t i0 = ((size_t)b * T_ + r0g) * C_ + col;
        size_t i1 = ((size_t)b * T_ + r0g + 8) * C_ + col;
        uint32_t hw0 = packbf(v0, v1);
        uint32_t lw0 = packbf(v0 - __uint_as_float(hw0 << 16),
                              v1 - __uint_as_float(hw0 & 0xFFFF0000u));
        uint32_t hw1 = packbf(v2, v3);
        uint32_t lw1 = packbf(v2 - __uint_as_float(hw1 << 16),
                              v3 - __uint_as_float(hw1 & 0xFFFF0000u));
        *(uint32_t*)(g_xhi + i0) = hw0;
        *(uint32_t*)(g_xlo + i0) = lw0;
        *(uint32_t*)(g_xhi + i1) = hw1;
        *(uint32_t*)(g_xlo + i1) = lw1;
    }
}

// ---------------------------------------------------------------------------
extern "C" void kernel_launch(void* const* d_in, const int* in_sizes, int n_in,
                              void* d_out, int out_size)
{
    const float* x  = (const float*)d_in[0];
    const float* Wk = (const float*)d_in[1];
    const float* bk = (const float*)d_in[2];
    const float* Wq = (const float*)d_in[3];
    const float* bq = (const float*)d_in[4];
    const float* Wv = (const float*)d_in[5];
    const float* bv = (const float*)d_in[6];
    const float* Wp = (const float*)d_in[7];
    const float* bp = (const float*)d_in[8];
    float* out = (float*)d_out;

    const int n4 = M_ * C_ / 4;
    conv_x_k<<<(n4 + 255) / 256, 256>>>(x, n4);

    dim3 tg(32, 32), tb(32, 8);
    conv_w_t_k<<<tg, tb>>>(Wq, 0);
    conv_w_t_k<<<tg, tb>>>(Wk, 1);
    conv_w_t_k<<<tg, tb>>>(Wv, 2);
    conv_w_t_k<<<tg, tb>>>(Wp, 3);

    const int smem_g = 3 * 40960;                    // 122880
    cudaFuncSetAttribute(gemm_qkv, cudaFuncAttributeMaxDynamicSharedMemorySize, smem_g);
    cudaFuncSetAttribute(gemm_out, cudaFuncAttributeMaxDynamicSharedMemorySize, smem_g);
    const int smem_a = 102400;
    cudaFuncSetAttribute(attn_mma, cudaFuncAttributeMaxDynamicSharedMemorySize, smem_a);

    gemm_qkv<<<dim3(M_ / 128, C_ / 128, 3), 256, smem_g>>>(bq, bk, bv);

    attn_mma<<<dim3(T_ / 128, B_ * H_), 256, smem_a>>>();

    gemm_out<<<dim3(M_ / 128, C_ / 128), 256, smem_g>>>(bp, out);
}

// round 12
// speedup vs baseline: 1.1831x; 1.1831x over previous
#include <cuda_runtime.h>
#include <cuda_bf16.h>
#include <cstdint>

#define B_ 4
#define T_ 2048
#define C_ 1024
#define H_ 16
#define D_ 64
#define M_ (B_*T_)   // 8192

// ---------------------------------------------------------------------------
// Scratch (__device__ globals; referenced ONLY from device code — host-side
// use of these symbols yields the host shadow (ATS zeros): round-5/6 bug)
// ---------------------------------------------------------------------------
__device__ float g_q[(size_t)B_*H_*T_*D_];
__device__ float g_k[(size_t)B_*H_*T_*D_];
__device__ float g_v[(size_t)B_*H_*T_*D_];
__device__ __align__(16) unsigned short g_xhi[(size_t)M_*C_];  // x split, then y split
__device__ __align__(16) unsigned short g_xlo[(size_t)M_*C_];
__device__ __align__(16) unsigned short g_whiT[(size_t)4*C_*C_];  // [slot][n][k]
__device__ __align__(16) unsigned short g_wloT[(size_t)4*C_*C_];

// ---------------------------------------------------------------------------
// Base-target PTX helpers
// ---------------------------------------------------------------------------
__device__ __forceinline__ uint32_t s2u(const void* p) {
    uint32_t a;
    asm("{ .reg .u64 t; cvta.to.shared.u64 t, %1; cvt.u32.u64 %0, t; }" : "=r"(a) : "l"(p));
    return a;
}

__device__ __forceinline__ void ldsm_x4(uint32_t addr, uint32_t* r) {
    asm volatile("ldmatrix.sync.aligned.m8n8.x4.shared.b16 {%0,%1,%2,%3}, [%4];"
                 : "=r"(r[0]), "=r"(r[1]), "=r"(r[2]), "=r"(r[3]) : "r"(addr));
}
__device__ __forceinline__ void ldsm_x4t(uint32_t addr, uint32_t* r) {
    asm volatile("ldmatrix.sync.aligned.m8n8.x4.trans.shared.b16 {%0,%1,%2,%3}, [%4];"
                 : "=r"(r[0]), "=r"(r[1]), "=r"(r[2]), "=r"(r[3]) : "r"(addr));
}

__device__ __forceinline__ void mma_bf16(float* c, const uint32_t* a, uint32_t b0, uint32_t b1) {
    asm("mma.sync.aligned.m16n8k16.row.col.f32.bf16.bf16.f32 "
        "{%0,%1,%2,%3}, {%4,%5,%6,%7}, {%8,%9}, {%0,%1,%2,%3};"
        : "+f"(c[0]), "+f"(c[1]), "+f"(c[2]), "+f"(c[3])
        : "r"(a[0]), "r"(a[1]), "r"(a[2]), "r"(a[3]), "r"(b0), "r"(b1));
}

__device__ __forceinline__ void cp16(uint32_t saddr, const void* g) {
    asm volatile("cp.async.cg.shared.global [%0], [%1], 16;" :: "r"(saddr), "l"(g));
}
#define CP_COMMIT() asm volatile("cp.async.commit_group;")

// pack two floats to bf16x2: low 16 bits = lo arg, high 16 bits = hi arg
__device__ __forceinline__ uint32_t packbf(float lo, float hi) {
    uint32_t r;
    asm("cvt.rn.bf16x2.f32 %0, %1, %2;" : "=r"(r) : "f"(hi), "f"(lo));
    return r;
}

// ---------------------------------------------------------------------------
// Conversion pre-passes
// ---------------------------------------------------------------------------
__global__ __launch_bounds__(256) void conv_x_k(const float* __restrict__ in, int n4)
{
    int i = blockIdx.x * blockDim.x + threadIdx.x;
    if (i >= n4) return;
    float4 v = ((const float4*)in)[i];
    uint32_t h0 = packbf(v.x, v.y);
    uint32_t h1 = packbf(v.z, v.w);
    float r0 = v.x - __uint_as_float(h0 << 16);
    float r1 = v.y - __uint_as_float(h0 & 0xFFFF0000u);
    float r2 = v.z - __uint_as_float(h1 << 16);
    float r3 = v.w - __uint_as_float(h1 & 0xFFFF0000u);
    ((uint2*)g_xhi)[i] = make_uint2(h0, h1);
    ((uint2*)g_xlo)[i] = make_uint2(packbf(r0, r1), packbf(r2, r3));
}

// W[k][n] -> WT hi/lo [n][k]
__global__ void conv_w_t_k(const float* __restrict__ W, int slot)
{
    __shared__ float tile[32][33];
    const int n0 = blockIdx.x * 32, k0 = blockIdx.y * 32;
    const int tx = threadIdx.x, ty = threadIdx.y;
    unsigned short* hiT = g_whiT + (size_t)slot * C_ * C_;
    unsigned short* loT = g_wloT + (size_t)slot * C_ * C_;
    for (int r = ty; r < 32; r += 8)
        tile[r][tx] = W[(size_t)(k0 + r) * C_ + n0 + tx];
    __syncthreads();
    for (int r = ty; r < 32; r += 8) {
        float v = tile[tx][r];
        __nv_bfloat16 h = __float2bfloat16_rn(v);
        float res = v - __bfloat162float(h);
        size_t o = (size_t)(n0 + r) * C_ + k0 + tx;
        hiT[o] = __bfloat16_as_ushort(h);
        loT[o] = __bfloat16_as_ushort(__float2bfloat16_rn(res));
    }
}

// ---------------------------------------------------------------------------
// GEMM body (split-bf16, mma.sync). 2-stage cp.async double buffer,
// ONE __syncthreads per K-iter (barrier precedes next-stage issue, covering
// both stage-ready and buffer-reuse hazards). smem 81920 B -> 2 CTAs/SM.
// dst 0/1/2: head-scatter fp32 into g_q/g_k/g_v; dst 3: plain fp32 to OutP.
// ---------------------------------------------------------------------------
__device__ __forceinline__
void gemm_body(int dst, const float* __restrict__ bias, float* __restrict__ OutP)
{
    extern __shared__ __align__(16) char sm[];
    const uint32_t smb = s2u(sm);
    const int tid = threadIdx.x, lane = tid & 31, wid = tid >> 5;
    const int warp_m = wid >> 2, warp_n = wid & 3;
    const int m0 = blockIdx.x * 128, n0 = blockIdx.y * 128;

    const unsigned short* Ahi = g_xhi;
    const unsigned short* Alo = g_xlo;
    const unsigned short* Bhi = g_whiT + (size_t)dst * C_ * C_;
    const unsigned short* Blo = g_wloT + (size_t)dst * C_ * C_;

    const unsigned short* gsrc[8];
    uint32_t sdst[8];
#pragma unroll
    for (int i = 0; i < 8; i++) {
        const int op  = i >> 1;                      // 0 Ahi,1 Alo,2 Bhi,3 Blo
        const int row = (tid >> 2) + (i & 1) * 64;
        const int seg = tid & 3;
        const unsigned short* base = (op == 0) ? Ahi : (op == 1) ? Alo : (op == 2) ? Bhi : Blo;
        const int grow = ((op < 2) ? m0 : n0) + row;
        gsrc[i] = base + (size_t)grow * C_ + seg * 8;
        sdst[i] = smb + op * 10240 + row * 80 + seg * 16;
    }

    float c[4][4][4];
#pragma unroll
    for (int mt = 0; mt < 4; mt++)
#pragma unroll
        for (int nt = 0; nt < 4; nt++)
#pragma unroll
            for (int e = 0; e < 4; e++) c[mt][nt][e] = 0.f;

    // prologue: stage 0
#pragma unroll
    for (int i = 0; i < 8; i++) cp16(sdst[i], gsrc[i]);
    CP_COMMIT();

    for (int it = 0; it < 32; ++it) {
        asm volatile("cp.async.wait_group 0;");   // stage it landed (this thread)
        __syncthreads();                          // visible to all; prev reads done

        if (it + 1 < 32) {                        // issue next AFTER barrier
            const uint32_t off = ((it + 1) & 1) * 40960;
#pragma unroll
            for (int i = 0; i < 8; i++) cp16(sdst[i] + off, gsrc[i] + (it + 1) * 32);
            CP_COMMIT();
        }

        const uint32_t sb = smb + (it & 1) * 40960;
#pragma unroll
        for (int kk = 0; kk < 2; kk++) {
            uint32_t ah[4][4], al[4][4], bh[4][2], bl[4][2];
#pragma unroll
            for (int mt = 0; mt < 4; mt++) {
                int row = warp_m * 64 + mt * 16 + (lane & 7) + ((lane >> 3) & 1) * 8;
                uint32_t byte = (uint32_t)(row * 80 + kk * 32 + (lane >> 4) * 16);
                ldsm_x4(sb + byte, ah[mt]);
                ldsm_x4(sb + 10240 + byte, al[mt]);
            }
#pragma unroll
            for (int p = 0; p < 2; p++) {
                int row = warp_n * 32 + p * 16 + (lane & 7) + ((lane >> 3) & 1) * 8;
                uint32_t byte = (uint32_t)(row * 80 + kk * 32 + (lane >> 4) * 16);
                uint32_t r[4], u[4];
                ldsm_x4(sb + 20480 + byte, r);
                ldsm_x4(sb + 30720 + byte, u);
                bh[2*p][0] = r[0]; bh[2*p][1] = r[2];
                bh[2*p+1][0] = r[1]; bh[2*p+1][1] = r[3];
                bl[2*p][0] = u[0]; bl[2*p][1] = u[2];
                bl[2*p+1][0] = u[1]; bl[2*p+1][1] = u[3];
            }
#pragma unroll
            for (int mt = 0; mt < 4; mt++)
#pragma unroll
                for (int nt = 0; nt < 4; nt++) {
                    mma_bf16(c[mt][nt], ah[mt], bh[nt][0], bh[nt][1]);
                    mma_bf16(c[mt][nt], ah[mt], bl[nt][0], bl[nt][1]);
                    mma_bf16(c[mt][nt], al[mt], bh[nt][0], bh[nt][1]);
                }
        }
    }

    // fp32 epilogue
#pragma unroll
    for (int mt = 0; mt < 4; mt++) {
        const int r = m0 + warp_m * 64 + mt * 16 + (lane >> 2);
#pragma unroll
        for (int nt = 0; nt < 4; nt++) {
            const int col = n0 + warp_n * 32 + nt * 8 + (lane & 3) * 2;
            const float bb0 = bias[col], bb1 = bias[col + 1];
#pragma unroll
            for (int half = 0; half < 2; half++) {
                const int m = r + half * 8;
                float v0 = c[mt][nt][half * 2 + 0] + bb0;
                float v1 = c[mt][nt][half * 2 + 1] + bb1;
                if (dst == 3) {
                    *(float2*)(OutP + (size_t)m * C_ + col) = make_float2(v0, v1);
                } else {
                    float* O = (dst == 0) ? g_q : (dst == 1) ? g_k : g_v;
                    const int b = m >> 11, t = m & (T_ - 1);
                    const int h = col >> 6, d = col & 63;
                    *(float2*)(O + (((size_t)(b * H_ + h)) * T_ + t) * D_ + d) = make_float2(v0, v1);
                }
            }
        }
    }
}

__global__ __launch_bounds__(256)
void gemm_qkv(const float* __restrict__ bq, const float* __restrict__ bk,
              const float* __restrict__ bv)
{
    const int z = blockIdx.z;
    const float* bias = (z == 0) ? bq : (z == 1) ? bk : bv;
    gemm_body(z, bias, nullptr);
}

__global__ __launch_bounds__(256)
void gemm_out(const float* __restrict__ bias, float* __restrict__ OutP)
{
    gemm_body(3, bias, OutP);
}

// ---------------------------------------------------------------------------
// Causal flash attention via mma.sync (round-8 structure: 4 warps, 64x64
// tiles, 36864 B static smem -> high CTA/SM residency). Reads fp32 g_q/g_k/g_v,
// converts tiles to split-bf16 in smem (Q scaled 1/8). Epilogue writes split
// y directly into g_xhi/g_xlo (feeds gemm_out; no conv pass, no g_y).
// smem: KH | KL | VH | VL, 64 rows x 144B stride each. Q staged in KH/KL.
// ---------------------------------------------------------------------------
__global__ __launch_bounds__(128)
void attn_mma()
{
    __shared__ __align__(16) char sm[4 * 64 * 144];
    const uint32_t smb = s2u(sm);
    const int tid = threadIdx.x, lane = tid & 31, warp = tid >> 5;
    const int qb = blockIdx.x, bh = blockIdx.y;

    const float* Qg = g_q + (size_t)bh * T_ * D_ + (size_t)qb * 64 * D_;
    const float* Kg = g_k + (size_t)bh * T_ * D_;
    const float* Vg = g_v + (size_t)bh * T_ * D_;

    // ---- stage Q tile (scaled by 1/8), split hi/lo into KH/KL buffers ----
#pragma unroll
    for (int i = 0; i < 8; i++) {
        int idx = i * 128 + tid;                  // float4 index, 1024 total
        float4 v = ((const float4*)Qg)[idx];
        v.x *= 0.125f; v.y *= 0.125f; v.z *= 0.125f; v.w *= 0.125f;
        uint32_t h0 = packbf(v.x, v.y), h1 = packbf(v.z, v.w);
        uint32_t l0 = packbf(v.x - __uint_as_float(h0 << 16),
                             v.y - __uint_as_float(h0 & 0xFFFF0000u));
        uint32_t l1 = packbf(v.z - __uint_as_float(h1 << 16),
                             v.w - __uint_as_float(h1 & 0xFFFF0000u));
        int row = idx >> 4, c8 = (idx & 15) * 8;
        *(uint2*)(sm + row * 144 + c8) = make_uint2(h0, h1);           // KH
        *(uint2*)(sm + 9216 + row * 144 + c8) = make_uint2(l0, l1);    // KL
    }
    __syncthreads();

    uint32_t qhf[4][4], qlf[4][4];
#pragma unroll
    for (int kk = 0; kk < 4; kk++) {
        int row = warp * 16 + (lane & 7) + ((lane >> 3) & 1) * 8;
        uint32_t byte = (uint32_t)(row * 144 + kk * 32 + (lane >> 4) * 16);
        ldsm_x4(smb + byte, qhf[kk]);
        ldsm_x4(smb + 9216 + byte, qlf[kk]);
    }
    __syncthreads();

    float o[8][4];
#pragma unroll
    for (int j = 0; j < 8; j++)
#pragma unroll
        for (int e = 0; e < 4; e++) o[j][e] = 0.f;
    float m0r = -1e30f, m1r = -1e30f, l0r = 0.f, l1r = 0.f;

    for (int kb = 0; kb <= qb; kb++) {
        // ---- load K/V fp32, convert to split-bf16 smem tiles ----
#pragma unroll
        for (int i = 0; i < 8; i++) {
            int idx = i * 128 + tid;
            int row = idx >> 4, c8 = (idx & 15) * 8;
            {
                float4 v = ((const float4*)(Kg + (size_t)kb * 64 * D_))[idx];
                uint32_t h0 = packbf(v.x, v.y), h1 = packbf(v.z, v.w);
                uint32_t l0 = packbf(v.x - __uint_as_float(h0 << 16),
                                     v.y - __uint_as_float(h0 & 0xFFFF0000u));
                uint32_t l1 = packbf(v.z - __uint_as_float(h1 << 16),
                                     v.w - __uint_as_float(h1 & 0xFFFF0000u));
                *(uint2*)(sm + row * 144 + c8) = make_uint2(h0, h1);
                *(uint2*)(sm + 9216 + row * 144 + c8) = make_uint2(l0, l1);
            }
            {
                float4 v = ((const float4*)(Vg + (size_t)kb * 64 * D_))[idx];
                uint32_t h0 = packbf(v.x, v.y), h1 = packbf(v.z, v.w);
                uint32_t l0 = packbf(v.x - __uint_as_float(h0 << 16),
                                     v.y - __uint_as_float(h0 & 0xFFFF0000u));
                uint32_t l1 = packbf(v.z - __uint_as_float(h1 << 16),
                                     v.w - __uint_as_float(h1 & 0xFFFF0000u));
                *(uint2*)(sm + 18432 + row * 144 + c8) = make_uint2(h0, h1);
                *(uint2*)(sm + 27648 + row * 144 + c8) = make_uint2(l0, l1);
            }
        }
        __syncthreads();

        // ---- S = Q K^T (3-term split) ----
        float s[8][4];
#pragma unroll
        for (int j = 0; j < 8; j++)
#pragma unroll
            for (int e = 0; e < 4; e++) s[j][e] = 0.f;

#pragma unroll
        for (int kk = 0; kk < 4; kk++) {
            uint32_t kh[8][2], kl[8][2];
#pragma unroll
            for (int p = 0; p < 4; p++) {
                int row = p * 16 + (lane & 7) + ((lane >> 3) & 1) * 8;
                uint32_t byte = (uint32_t)(row * 144 + kk * 32 + (lane >> 4) * 16);
                uint32_t r[4], u[4];
                ldsm_x4(smb + byte, r);          // KH
                ldsm_x4(smb + 9216 + byte, u);   // KL
                kh[2*p][0] = r[0]; kh[2*p][1] = r[2];
                kh[2*p+1][0] = r[1]; kh[2*p+1][1] = r[3];
                kl[2*p][0] = u[0]; kl[2*p][1] = u[2];
                kl[2*p+1][0] = u[1]; kl[2*p+1][1] = u[3];
            }
#pragma unroll
            for (int j = 0; j < 8; j++) {
                mma_bf16(s[j], qhf[kk], kh[j][0], kh[j][1]);
                mma_bf16(s[j], qhf[kk], kl[j][0], kl[j][1]);
                mma_bf16(s[j], qlf[kk], kh[j][0], kh[j][1]);
            }
        }

        // ---- causal mask on diagonal block ----
        if (kb == qb) {
            const int r0 = warp * 16 + (lane >> 2);
#pragma unroll
            for (int j = 0; j < 8; j++) {
#pragma unroll
                for (int e = 0; e < 4; e++) {
                    int col = j * 8 + (lane & 3) * 2 + (e & 1);
                    int row = r0 + (e >> 1) * 8;
                    if (col > row) s[j][e] = -1e30f;
                }
            }
        }

        // ---- online softmax (per-lane rows + quad reduction) ----
        float mt0 = -1e30f, mt1 = -1e30f;
#pragma unroll
        for (int j = 0; j < 8; j++) {
            mt0 = fmaxf(mt0, fmaxf(s[j][0], s[j][1]));
            mt1 = fmaxf(mt1, fmaxf(s[j][2], s[j][3]));
        }
        mt0 = fmaxf(mt0, __shfl_xor_sync(0xffffffffu, mt0, 1));
        mt0 = fmaxf(mt0, __shfl_xor_sync(0xffffffffu, mt0, 2));
        mt1 = fmaxf(mt1, __shfl_xor_sync(0xffffffffu, mt1, 1));
        mt1 = fmaxf(mt1, __shfl_xor_sync(0xffffffffu, mt1, 2));
        const float mn0 = fmaxf(m0r, mt0), mn1 = fmaxf(m1r, mt1);
        const float al0 = __expf(m0r - mn0), al1 = __expf(m1r - mn1);

        float ls0 = 0.f, ls1 = 0.f;
        uint32_t aph[4][4], apl[4][4];
#pragma unroll
        for (int j = 0; j < 8; j++) {
            float p0 = __expf(s[j][0] - mn0);
            float p1 = __expf(s[j][1] - mn0);
            float p2 = __expf(s[j][2] - mn1);
            float p3 = __expf(s[j][3] - mn1);
            ls0 += p0 + p1;
            ls1 += p2 + p3;
            uint32_t h01 = packbf(p0, p1), h23 = packbf(p2, p3);
            float e0 = p0 - __uint_as_float(h01 << 16);
            float e1 = p1 - __uint_as_float(h01 & 0xFFFF0000u);
            float e2 = p2 - __uint_as_float(h23 << 16);
            float e3 = p3 - __uint_as_float(h23 & 0xFFFF0000u);
            uint32_t l01 = packbf(e0, e1), l23 = packbf(e2, e3);
            const int kk = j >> 1;
            if ((j & 1) == 0) {
                aph[kk][0] = h01; aph[kk][1] = h23;
                apl[kk][0] = l01; apl[kk][1] = l23;
            } else {
                aph[kk][2] = h01; aph[kk][3] = h23;
                apl[kk][2] = l01; apl[kk][3] = l23;
            }
        }
        ls0 += __shfl_xor_sync(0xffffffffu, ls0, 1);
        ls0 += __shfl_xor_sync(0xffffffffu, ls0, 2);
        ls1 += __shfl_xor_sync(0xffffffffu, ls1, 1);
        ls1 += __shfl_xor_sync(0xffffffffu, ls1, 2);
        l0r = l0r * al0 + ls0;
        l1r = l1r * al1 + ls1;
        m0r = mn0; m1r = mn1;

#pragma unroll
        for (int j = 0; j < 8; j++) {
            o[j][0] *= al0; o[j][1] *= al0;
            o[j][2] *= al1; o[j][3] *= al1;
        }

        // ---- O += P V (3-term split) ----
#pragma unroll
        for (int kk = 0; kk < 4; kk++) {
#pragma unroll
            for (int j = 0; j < 8; j += 2) {
                int row = kk * 16 + (lane & 7) + ((lane >> 3) & 1) * 8;
                uint32_t byte = (uint32_t)(row * 144 + (j + (lane >> 4)) * 16);
                uint32_t r[4], u[4];
                ldsm_x4t(smb + 18432 + byte, r);   // VH
                ldsm_x4t(smb + 27648 + byte, u);   // VL
                mma_bf16(o[j],     aph[kk], r[0], r[1]);
                mma_bf16(o[j],     aph[kk], u[0], u[1]);
                mma_bf16(o[j],     apl[kk], r[0], r[1]);
                mma_bf16(o[j + 1], aph[kk], r[2], r[3]);
                mma_bf16(o[j + 1], aph[kk], u[2], u[3]);
                mma_bf16(o[j + 1], apl[kk], r[2], r[3]);
            }
        }
        __syncthreads();
    }

    // ---- epilogue: normalize, split, write y hi/lo directly (no conv pass) ----
    const float inv0 = 1.f / l0r, inv1 = 1.f / l1r;
    const int b = bh >> 4, h = bh & 15;
    const int r0g = qb * 64 + warp * 16 + (lane >> 2);
#pragma unroll
    for (int j = 0; j < 8; j++) {
        const int col = h * 64 + j * 8 + (lane & 3) * 2;
        float v0 = o[j][0] * inv0, v1 = o[j][1] * inv0;
        float v2 = o[j][2] * inv1, v3 = o[j][3] * inv1;
        size_t i0 = ((size_t)b * T_ + r0g) * C_ + col;
        size_t i1 = ((size_t)b * T_ + r0g + 8) * C_ + col;
        uint32_t hw0 = packbf(v0, v1);
        uint32_t lw0 = packbf(v0 - __uint_as_float(hw0 << 16),
                              v1 - __uint_as_float(hw0 & 0xFFFF0000u));
        uint32_t hw1 = packbf(v2, v3);
        uint32_t lw1 = packbf(v2 - __uint_as_float(hw1 << 16),
                              v3 - __uint_as_float(hw1 & 0xFFFF0000u));
        *(uint32_t*)(g_xhi + i0) = hw0;
        *(uint32_t*)(g_xlo + i0) = lw0;
        *(uint32_t*)(g_xhi + i1) = hw1;
        *(uint32_t*)(g_xlo + i1) = lw1;
    }
}

// ---------------------------------------------------------------------------
extern "C" void kernel_launch(void* const* d_in, const int* in_sizes, int n_in,
                              void* d_out, int out_size)
{
    const float* x  = (const float*)d_in[0];
    const float* Wk = (const float*)d_in[1];
    const float* bk = (const float*)d_in[2];
    const float* Wq = (const float*)d_in[3];
    const float* bq = (const float*)d_in[4];
    const float* Wv = (const float*)d_in[5];
    const float* bv = (const float*)d_in[6];
    const float* Wp = (const float*)d_in[7];
    const float* bp = (const float*)d_in[8];
    float* out = (float*)d_out;

    const int n4 = M_ * C_ / 4;
    conv_x_k<<<(n4 + 255) / 256, 256>>>(x, n4);

    dim3 tg(32, 32), tb(32, 8);
    conv_w_t_k<<<tg, tb>>>(Wq, 0);
    conv_w_t_k<<<tg, tb>>>(Wk, 1);
    conv_w_t_k<<<tg, tb>>>(Wv, 2);
    conv_w_t_k<<<tg, tb>>>(Wp, 3);

    const int smem_g = 81920;
    cudaFuncSetAttribute(gemm_qkv, cudaFuncAttributeMaxDynamicSharedMemorySize, smem_g);
    cudaFuncSetAttribute(gemm_out, cudaFuncAttributeMaxDynamicSharedMemorySize, smem_g);

    gemm_qkv<<<dim3(M_ / 128, C_ / 128, 3), 256, smem_g>>>(bq, bk, bv);

    attn_mma<<<dim3(T_ / 64, B_ * H_), 128>>>();

    gemm_out<<<dim3(M_ / 128, C_ / 128), 256, smem_g>>>(bp, out);
}

// round 14
// speedup vs baseline: 1.2937x; 1.0935x over previous
#include <cuda_runtime.h>
#include <cuda_bf16.h>
#include <cstdint>

#define B_ 4
#define T_ 2048
#define C_ 1024
#define H_ 16
#define D_ 64
#define M_ (B_*T_)   // 8192

// ---------------------------------------------------------------------------
// Scratch (__device__ globals; referenced ONLY from device code — host-side
// use of these symbols yields the host shadow (ATS zeros): round-5/6 bug)
// ---------------------------------------------------------------------------
__device__ float g_q[(size_t)B_*H_*T_*D_];
__device__ float g_k[(size_t)B_*H_*T_*D_];
__device__ float g_v[(size_t)B_*H_*T_*D_];
__device__ __align__(16) unsigned short g_xhi[(size_t)M_*C_];  // x split, then y split
__device__ __align__(16) unsigned short g_xlo[(size_t)M_*C_];
__device__ __align__(16) unsigned short g_whiT[(size_t)4*C_*C_];  // [slot][n][k]
__device__ __align__(16) unsigned short g_wloT[(size_t)4*C_*C_];

// ---------------------------------------------------------------------------
// Base-target PTX helpers
// ---------------------------------------------------------------------------
__device__ __forceinline__ uint32_t s2u(const void* p) {
    uint32_t a;
    asm("{ .reg .u64 t; cvta.to.shared.u64 t, %1; cvt.u32.u64 %0, t; }" : "=r"(a) : "l"(p));
    return a;
}

__device__ __forceinline__ void ldsm_x4(uint32_t addr, uint32_t* r) {
    asm volatile("ldmatrix.sync.aligned.m8n8.x4.shared.b16 {%0,%1,%2,%3}, [%4];"
                 : "=r"(r[0]), "=r"(r[1]), "=r"(r[2]), "=r"(r[3]) : "r"(addr));
}
__device__ __forceinline__ void ldsm_x4t(uint32_t addr, uint32_t* r) {
    asm volatile("ldmatrix.sync.aligned.m8n8.x4.trans.shared.b16 {%0,%1,%2,%3}, [%4];"
                 : "=r"(r[0]), "=r"(r[1]), "=r"(r[2]), "=r"(r[3]) : "r"(addr));
}

__device__ __forceinline__ void mma_bf16(float* c, const uint32_t* a, uint32_t b0, uint32_t b1) {
    asm("mma.sync.aligned.m16n8k16.row.col.f32.bf16.bf16.f32 "
        "{%0,%1,%2,%3}, {%4,%5,%6,%7}, {%8,%9}, {%0,%1,%2,%3};"
        : "+f"(c[0]), "+f"(c[1]), "+f"(c[2]), "+f"(c[3])
        : "r"(a[0]), "r"(a[1]), "r"(a[2]), "r"(a[3]), "r"(b0), "r"(b1));
}

__device__ __forceinline__ void cp16(uint32_t saddr, const void* g) {
    asm volatile("cp.async.cg.shared.global [%0], [%1], 16;" :: "r"(saddr), "l"(g));
}
#define CP_COMMIT() asm volatile("cp.async.commit_group;")

// pack two floats to bf16x2: low 16 bits = lo arg, high 16 bits = hi arg
__device__ __forceinline__ uint32_t packbf(float lo, float hi) {
    uint32_t r;
    asm("cvt.rn.bf16x2.f32 %0, %1, %2;" : "=r"(r) : "f"(hi), "f"(lo));
    return r;
}

// GEMM smem geometry: rows of 64B (K=32 bf16), XOR-swizzled 16B chunks.
// swz(row, c): chunk c in {0..3}; conflict-free for ldsm row groups of 8.
__device__ __forceinline__ uint32_t swz(int row, int c) {
    return (uint32_t)(row * 64 + ((c ^ ((row >> 1) & 3)) << 4));
}
#define G_OPST 8192u     // per-operand stride (128 rows x 64B)
#define G_STG  32768u    // per-stage stride (4 operands)

// ---------------------------------------------------------------------------
// Conversion pre-passes
// ---------------------------------------------------------------------------
__global__ __launch_bounds__(256) void conv_x_k(const float* __restrict__ in, int n4)
{
    int i = blockIdx.x * blockDim.x + threadIdx.x;
    if (i >= n4) return;
    float4 v = ((const float4*)in)[i];
    uint32_t h0 = packbf(v.x, v.y);
    uint32_t h1 = packbf(v.z, v.w);
    float r0 = v.x - __uint_as_float(h0 << 16);
    float r1 = v.y - __uint_as_float(h0 & 0xFFFF0000u);
    float r2 = v.z - __uint_as_float(h1 << 16);
    float r3 = v.w - __uint_as_float(h1 & 0xFFFF0000u);
    ((uint2*)g_xhi)[i] = make_uint2(h0, h1);
    ((uint2*)g_xlo)[i] = make_uint2(packbf(r0, r1), packbf(r2, r3));
}

// W[k][n] -> WT hi/lo [n][k]; all 4 weights in one launch (blockIdx.z = slot)
__global__ void conv_w_t_k(const float* __restrict__ Wq, const float* __restrict__ Wk,
                           const float* __restrict__ Wv, const float* __restrict__ Wp)
{
    __shared__ float tile[32][33];
    const int slot = blockIdx.z;
    const float* W = (slot == 0) ? Wq : (slot == 1) ? Wk : (slot == 2) ? Wv : Wp;
    const int n0 = blockIdx.x * 32, k0 = blockIdx.y * 32;
    const int tx = threadIdx.x, ty = threadIdx.y;
    unsigned short* hiT = g_whiT + (size_t)slot * C_ * C_;
    unsigned short* loT = g_wloT + (size_t)slot * C_ * C_;
    for (int r = ty; r < 32; r += 8)
        tile[r][tx] = W[(size_t)(k0 + r) * C_ + n0 + tx];
    __syncthreads();
    for (int r = ty; r < 32; r += 8) {
        float v = tile[tx][r];
        __nv_bfloat16 h = __float2bfloat16_rn(v);
        float res = v - __bfloat162float(h);
        size_t o = (size_t)(n0 + r) * C_ + k0 + tx;
        hiT[o] = __bfloat16_as_ushort(h);
        loT[o] = __bfloat16_as_ushort(__float2bfloat16_rn(res));
    }
}

// ---------------------------------------------------------------------------
// GEMM body (split-bf16, mma.sync). THREE-stage cp.async pipeline with
// swizzled 64B rows: stage = 32KB, 3 stages = 96KB -> still 2 CTAs/SM
// (enforced by __launch_bounds__(256,2)). wait_group 1 keeps one stage
// in flight behind compute. Barrier precedes next-stage issue (reuse-safe).
// dst 0/1/2: head-scatter fp32 into g_q/g_k/g_v; dst 3: plain fp32 to OutP.
// ---------------------------------------------------------------------------
__device__ __forceinline__
void gemm_body(int dst, const float* __restrict__ bias, float* __restrict__ OutP)
{
    extern __shared__ __align__(16) char sm[];
    const uint32_t smb = s2u(sm);
    const int tid = threadIdx.x, lane = tid & 31, wid = tid >> 5;
    const int warp_m = wid >> 2, warp_n = wid & 3;
    const int m0 = blockIdx.x * 128, n0 = blockIdx.y * 128;

    const unsigned short* Ahi = g_xhi;
    const unsigned short* Alo = g_xlo;
    const unsigned short* Bhi = g_whiT + (size_t)dst * C_ * C_;
    const unsigned short* Blo = g_wloT + (size_t)dst * C_ * C_;

    const unsigned short* gsrc[8];
    uint32_t sdst[8];
#pragma unroll
    for (int i = 0; i < 8; i++) {
        const int op  = i >> 1;                      // 0 Ahi,1 Alo,2 Bhi,3 Blo
        const int row = (tid >> 2) + (i & 1) * 64;
        const int seg = tid & 3;
        const unsigned short* base = (op == 0) ? Ahi : (op == 1) ? Alo : (op == 2) ? Bhi : Blo;
        const int grow = ((op < 2) ? m0 : n0) + row;
        gsrc[i] = base + (size_t)grow * C_ + seg * 8;
        sdst[i] = smb + op * G_OPST + swz(row, seg);
    }

    float c[4][4][4];
#pragma unroll
    for (int mt = 0; mt < 4; mt++)
#pragma unroll
        for (int nt = 0; nt < 4; nt++)
#pragma unroll
            for (int e = 0; e < 4; e++) c[mt][nt][e] = 0.f;

    // prologue: stages 0, 1
#pragma unroll
    for (int i = 0; i < 8; i++) cp16(sdst[i], gsrc[i]);
    CP_COMMIT();
#pragma unroll
    for (int i = 0; i < 8; i++) cp16(sdst[i] + G_STG, gsrc[i] + 32);
    CP_COMMIT();

    for (int it = 0; it < 32; ++it) {
        if (it < 31) asm volatile("cp.async.wait_group 1;");  // stage it done
        else         asm volatile("cp.async.wait_group 0;");
        __syncthreads();                          // ready + prior reads retired

        if (it + 2 < 32) {                        // issue stage it+2 AFTER barrier
            const uint32_t off = ((it + 2) % 3) * G_STG;
#pragma unroll
            for (int i = 0; i < 8; i++) cp16(sdst[i] + off, gsrc[i] + (it + 2) * 32);
            CP_COMMIT();
        }

        const uint32_t sb = smb + (it % 3) * G_STG;
#pragma unroll
        for (int kk = 0; kk < 2; kk++) {
            const int cc = kk * 2 + (lane >> 4);          // 16B chunk 0..3
            uint32_t ah[4][4], al[4][4], bh[4][2], bl[4][2];
#pragma unroll
            for (int mt = 0; mt < 4; mt++) {
                int row = warp_m * 64 + mt * 16 + (lane & 7) + ((lane >> 3) & 1) * 8;
                uint32_t byte = swz(row, cc);
                ldsm_x4(sb + byte, ah[mt]);
                ldsm_x4(sb + G_OPST + byte, al[mt]);
            }
#pragma unroll
            for (int p = 0; p < 2; p++) {
                int row = warp_n * 32 + p * 16 + (lane & 7) + ((lane >> 3) & 1) * 8;
                uint32_t byte = swz(row, cc);
                uint32_t r[4], u[4];
                ldsm_x4(sb + 2 * G_OPST + byte, r);
                ldsm_x4(sb + 3 * G_OPST + byte, u);
                bh[2*p][0] = r[0]; bh[2*p][1] = r[2];
                bh[2*p+1][0] = r[1]; bh[2*p+1][1] = r[3];
                bl[2*p][0] = u[0]; bl[2*p][1] = u[2];
                bl[2*p+1][0] = u[1]; bl[2*p+1][1] = u[3];
            }
#pragma unroll
            for (int mt = 0; mt < 4; mt++)
#pragma unroll
                for (int nt = 0; nt < 4; nt++) {
                    mma_bf16(c[mt][nt], ah[mt], bh[nt][0], bh[nt][1]);
                    mma_bf16(c[mt][nt], ah[mt], bl[nt][0], bl[nt][1]);
                    mma_bf16(c[mt][nt], al[mt], bh[nt][0], bh[nt][1]);
                }
        }
    }

    // fp32 epilogue
#pragma unroll
    for (int mt = 0; mt < 4; mt++) {
        const int r = m0 + warp_m * 64 + mt * 16 + (lane >> 2);
#pragma unroll
        for (int nt = 0; nt < 4; nt++) {
            const int col = n0 + warp_n * 32 + nt * 8 + (lane & 3) * 2;
            const float bb0 = bias[col], bb1 = bias[col + 1];
#pragma unroll
            for (int half = 0; half < 2; half++) {
                const int m = r + half * 8;
                float v0 = c[mt][nt][half * 2 + 0] + bb0;
                float v1 = c[mt][nt][half * 2 + 1] + bb1;
                if (dst == 3) {
                    *(float2*)(OutP + (size_t)m * C_ + col) = make_float2(v0, v1);
                } else {
                    float* O = (dst == 0) ? g_q : (dst == 1) ? g_k : g_v;
                    const int b = m >> 11, t = m & (T_ - 1);
                    const int h = col >> 6, d = col & 63;
                    *(float2*)(O + (((size_t)(b * H_ + h)) * T_ + t) * D_ + d) = make_float2(v0, v1);
                }
            }
        }
    }
}

__global__ __launch_bounds__(256, 2)
void gemm_qkv(const float* __restrict__ bq, const float* __restrict__ bk,
              const float* __restrict__ bv)
{
    const int z = blockIdx.z;
    const float* bias = (z == 0) ? bq : (z == 1) ? bk : bv;
    gemm_body(z, bias, nullptr);
}

__global__ __launch_bounds__(256, 2)
void gemm_out(const float* __restrict__ bias, float* __restrict__ OutP)
{
    gemm_body(3, bias, OutP);
}

// ---------------------------------------------------------------------------
// Causal flash attention via mma.sync (validated round-12 version, unchanged).
// ---------------------------------------------------------------------------
__global__ __launch_bounds__(128)
void attn_mma()
{
    __shared__ __align__(16) char sm[4 * 64 * 144];
    const uint32_t smb = s2u(sm);
    const int tid = threadIdx.x, lane = tid & 31, warp = tid >> 5;
    const int qb = blockIdx.x, bh = blockIdx.y;

    const float* Qg = g_q + (size_t)bh * T_ * D_ + (size_t)qb * 64 * D_;
    const float* Kg = g_k + (size_t)bh * T_ * D_;
    const float* Vg = g_v + (size_t)bh * T_ * D_;

    // ---- stage Q tile (scaled by 1/8), split hi/lo into KH/KL buffers ----
#pragma unroll
    for (int i = 0; i < 8; i++) {
        int idx = i * 128 + tid;                  // float4 index, 1024 total
        float4 v = ((const float4*)Qg)[idx];
        v.x *= 0.125f; v.y *= 0.125f; v.z *= 0.125f; v.w *= 0.125f;
        uint32_t h0 = packbf(v.x, v.y), h1 = packbf(v.z, v.w);
        uint32_t l0 = packbf(v.x - __uint_as_float(h0 << 16),
                             v.y - __uint_as_float(h0 & 0xFFFF0000u));
        uint32_t l1 = packbf(v.z - __uint_as_float(h1 << 16),
                             v.w - __uint_as_float(h1 & 0xFFFF0000u));
        int row = idx >> 4, c8 = (idx & 15) * 8;
        *(uint2*)(sm + row * 144 + c8) = make_uint2(h0, h1);           // KH
        *(uint2*)(sm + 9216 + row * 144 + c8) = make_uint2(l0, l1);    // KL
    }
    __syncthreads();

    uint32_t qhf[4][4], qlf[4][4];
#pragma unroll
    for (int kk = 0; kk < 4; kk++) {
        int row = warp * 16 + (lane & 7) + ((lane >> 3) & 1) * 8;
        uint32_t byte = (uint32_t)(row * 144 + kk * 32 + (lane >> 4) * 16);
        ldsm_x4(smb + byte, qhf[kk]);
        ldsm_x4(smb + 9216 + byte, qlf[kk]);
    }
    __syncthreads();

    float o[8][4];
#pragma unroll
    for (int j = 0; j < 8; j++)
#pragma unroll
        for (int e = 0; e < 4; e++) o[j][e] = 0.f;
    float m0r = -1e30f, m1r = -1e30f, l0r = 0.f, l1r = 0.f;

    for (int kb = 0; kb <= qb; kb++) {
        // ---- load K/V fp32, convert to split-bf16 smem tiles ----
#pragma unroll
        for (int i = 0; i < 8; i++) {
            int idx = i * 128 + tid;
            int row = idx >> 4, c8 = (idx & 15) * 8;
            {
                float4 v = ((const float4*)(Kg + (size_t)kb * 64 * D_))[idx];
                uint32_t h0 = packbf(v.x, v.y), h1 = packbf(v.z, v.w);
                uint32_t l0 = packbf(v.x - __uint_as_float(h0 << 16),
                                     v.y - __uint_as_float(h0 & 0xFFFF0000u));
                uint32_t l1 = packbf(v.z - __uint_as_float(h1 << 16),
                                     v.w - __uint_as_float(h1 & 0xFFFF0000u));
                *(uint2*)(sm + row * 144 + c8) = make_uint2(h0, h1);
                *(uint2*)(sm + 9216 + row * 144 + c8) = make_uint2(l0, l1);
            }
            {
                float4 v = ((const float4*)(Vg + (size_t)kb * 64 * D_))[idx];
                uint32_t h0 = packbf(v.x, v.y), h1 = packbf(v.z, v.w);
                uint32_t l0 = packbf(v.x - __uint_as_float(h0 << 16),
                                     v.y - __uint_as_float(h0 & 0xFFFF0000u));
                uint32_t l1 = packbf(v.z - __uint_as_float(h1 << 16),
                                     v.w - __uint_as_float(h1 & 0xFFFF0000u));
                *(uint2*)(sm + 18432 + row * 144 + c8) = make_uint2(h0, h1);
                *(uint2*)(sm + 27648 + row * 144 + c8) = make_uint2(l0, l1);
            }
        }
        __syncthreads();

        // ---- S = Q K^T (3-term split) ----
        float s[8][4];
#pragma unroll
        for (int j = 0; j < 8; j++)
#pragma unroll
            for (int e = 0; e < 4; e++) s[j][e] = 0.f;

#pragma unroll
        for (int kk = 0; kk < 4; kk++) {
            uint32_t kh[8][2], kl[8][2];
#pragma unroll
            for (int p = 0; p < 4; p++) {
                int row = p * 16 + (lane & 7) + ((lane >> 3) & 1) * 8;
                uint32_t byte = (uint32_t)(row * 144 + kk * 32 + (lane >> 4) * 16);
                uint32_t r[4], u[4];
                ldsm_x4(smb + byte, r);          // KH
                ldsm_x4(smb + 9216 + byte, u);   // KL
                kh[2*p][0] = r[0]; kh[2*p][1] = r[2];
                kh[2*p+1][0] = r[1]; kh[2*p+1][1] = r[3];
                kl[2*p][0] = u[0]; kl[2*p][1] = u[2];
                kl[2*p+1][0] = u[1]; kl[2*p+1][1] = u[3];
            }
#pragma unroll
            for (int j = 0; j < 8; j++) {
                mma_bf16(s[j], qhf[kk], kh[j][0], kh[j][1]);
                mma_bf16(s[j], qhf[kk], kl[j][0], kl[j][1]);
                mma_bf16(s[j], qlf[kk], kh[j][0], kh[j][1]);
            }
        }

        // ---- causal mask on diagonal block ----
        if (kb == qb) {
            const int r0 = warp * 16 + (lane >> 2);
#pragma unroll
            for (int j = 0; j < 8; j++) {
#pragma unroll
                for (int e = 0; e < 4; e++) {
                    int col = j * 8 + (lane & 3) * 2 + (e & 1);
                    int row = r0 + (e >> 1) * 8;
                    if (col > row) s[j][e] = -1e30f;
                }
            }
        }

        // ---- online softmax (per-lane rows + quad reduction) ----
        float mt0 = -1e30f, mt1 = -1e30f;
#pragma unroll
        for (int j = 0; j < 8; j++) {
            mt0 = fmaxf(mt0, fmaxf(s[j][0], s[j][1]));
            mt1 = fmaxf(mt1, fmaxf(s[j][2], s[j][3]));
        }
        mt0 = fmaxf(mt0, __shfl_xor_sync(0xffffffffu, mt0, 1));
        mt0 = fmaxf(mt0, __shfl_xor_sync(0xffffffffu, mt0, 2));
        mt1 = fmaxf(mt1, __shfl_xor_sync(0xffffffffu, mt1, 1));
        mt1 = fmaxf(mt1, __shfl_xor_sync(0xffffffffu, mt1, 2));
        const float mn0 = fmaxf(m0r, mt0), mn1 = fmaxf(m1r, mt1);
        const float al0 = __expf(m0r - mn0), al1 = __expf(m1r - mn1);

        float ls0 = 0.f, ls1 = 0.f;
        uint32_t aph[4][4], apl[4][4];
#pragma unroll
        for (int j = 0; j < 8; j++) {
            float p0 = __expf(s[j][0] - mn0);
            float p1 = __expf(s[j][1] - mn0);
            float p2 = __expf(s[j][2] - mn1);
            float p3 = __expf(s[j][3] - mn1);
            ls0 += p0 + p1;
            ls1 += p2 + p3;
            uint32_t h01 = packbf(p0, p1), h23 = packbf(p2, p3);
            float e0 = p0 - __uint_as_float(h01 << 16);
            float e1 = p1 - __uint_as_float(h01 & 0xFFFF0000u);
            float e2 = p2 - __uint_as_float(h23 << 16);
            float e3 = p3 - __uint_as_float(h23 & 0xFFFF0000u);
            uint32_t l01 = packbf(e0, e1), l23 = packbf(e2, e3);
            const int kk = j >> 1;
            if ((j & 1) == 0) {
                aph[kk][0] = h01; aph[kk][1] = h23;
                apl[kk][0] = l01; apl[kk][1] = l23;
            } else {
                aph[kk][2] = h01; aph[kk][3] = h23;
                apl[kk][2] = l01; apl[kk][3] = l23;
            }
        }
        ls0 += __shfl_xor_sync(0xffffffffu, ls0, 1);
        ls0 += __shfl_xor_sync(0xffffffffu, ls0, 2);
        ls1 += __shfl_xor_sync(0xffffffffu, ls1, 1);
        ls1 += __shfl_xor_sync(0xffffffffu, ls1, 2);
        l0r = l0r * al0 + ls0;
        l1r = l1r * al1 + ls1;
        m0r = mn0; m1r = mn1;

#pragma unroll
        for (int j = 0; j < 8; j++) {
            o[j][0] *= al0; o[j][1] *= al0;
            o[j][2] *= al1; o[j][3] *= al1;
        }

        // ---- O += P V (3-term split) ----
#pragma unroll
        for (int kk = 0; kk < 4; kk++) {
#pragma unroll
            for (int j = 0; j < 8; j += 2) {
                int row = kk * 16 + (lane & 7) + ((lane >> 3) & 1) * 8;
                uint32_t byte = (uint32_t)(row * 144 + (j + (lane >> 4)) * 16);
                uint32_t r[4], u[4];
                ldsm_x4t(smb + 18432 + byte, r);   // VH
                ldsm_x4t(smb + 27648 + byte, u);   // VL
                mma_bf16(o[j],     aph[kk], r[0], r[1]);
                mma_bf16(o[j],     aph[kk], u[0], u[1]);
                mma_bf16(o[j],     apl[kk], r[0], r[1]);
                mma_bf16(o[j + 1], aph[kk], r[2], r[3]);
                mma_bf16(o[j + 1], aph[kk], u[2], u[3]);
                mma_bf16(o[j + 1], apl[kk], r[2], r[3]);
            }
        }
        __syncthreads();
    }

    // ---- epilogue: normalize, split, write y hi/lo directly (no conv pass) ----
    const float inv0 = 1.f / l0r, inv1 = 1.f / l1r;
    const int b = bh >> 4, h = bh & 15;
    const int r0g = qb * 64 + warp * 16 + (lane >> 2);
#pragma unroll
    for (int j = 0; j < 8; j++) {
        const int col = h * 64 + j * 8 + (lane & 3) * 2;
        float v0 = o[j][0] * inv0, v1 = o[j][1] * inv0;
        float v2 = o[j][2] * inv1, v3 = o[j][3] * inv1;
        size_t i0 = ((size_t)b * T_ + r0g) * C_ + col;
        size_t i1 = ((size_t)b * T_ + r0g + 8) * C_ + col;
        uint32_t hw0 = packbf(v0, v1);
        uint32_t lw0 = packbf(v0 - __uint_as_float(hw0 << 16),
                              v1 - __uint_as_float(hw0 & 0xFFFF0000u));
        uint32_t hw1 = packbf(v2, v3);
        uint32_t lw1 = packbf(v2 - __uint_as_float(hw1 << 16),
                              v3 - __uint_as_float(hw1 & 0xFFFF0000u));
        *(uint32_t*)(g_xhi + i0) = hw0;
        *(uint32_t*)(g_xlo + i0) = lw0;
        *(uint32_t*)(g_xhi + i1) = hw1;
        *(uint32_t*)(g_xlo + i1) = lw1;
    }
}

// ---------------------------------------------------------------------------
extern "C" void kernel_launch(void* const* d_in, const int* in_sizes, int n_in,
                              void* d_out, int out_size)
{
    const float* x  = (const float*)d_in[0];
    const float* Wk = (const float*)d_in[1];
    const float* bk = (const float*)d_in[2];
    const float* Wq = (const float*)d_in[3];
    const float* bq = (const float*)d_in[4];
    const float* Wv = (const float*)d_in[5];
    const float* bv = (const float*)d_in[6];
    const float* Wp = (const float*)d_in[7];
    const float* bp = (const float*)d_in[8];
    float* out = (float*)d_out;

    const int n4 = M_ * C_ / 4;
    conv_x_k<<<(n4 + 255) / 256, 256>>>(x, n4);

    conv_w_t_k<<<dim3(32, 32, 4), dim3(32, 8)>>>(Wq, Wk, Wv, Wp);

    const int smem_g = 3 * G_STG;                    // 98304
    cudaFuncSetAttribute(gemm_qkv, cudaFuncAttributeMaxDynamicSharedMemorySize, smem_g);
    cudaFuncSetAttribute(gemm_out, cudaFuncAttributeMaxDynamicSharedMemorySize, smem_g);

    gemm_qkv<<<dim3(M_ / 128, C_ / 128, 3), 256, smem_g>>>(bq, bk, bv);

    attn_mma<<<dim3(T_ / 64, B_ * H_), 128>>>();

    gemm_out<<<dim3(M_ / 128, C_ / 128), 256, smem_g>>>(bp, out);
}